// round 14
// baseline (speedup 1.0000x reference)
#include <cuda_runtime.h>
#include <cuda_bf16.h>
#include <math.h>
#include <stdint.h>

// Problem constants
#define Bn   8
#define Hh   32
#define Ww   32
#define Cc   192
#define DI   384
#define Ss   16
#define Rr   12
#define HID  768
#define Ll   1024          // H*W
#define ROWS (Bn * Ll)     // 8192

typedef __nv_bfloat16 bf16;

// ---------------- scratch (no allocation allowed) ----------------
__device__ bf16  g_hx_bf [ROWS * Cc];
__device__ float g_xz    [ROWS * (2 * DI)];
__device__ float g_u     [ROWS * DI];
__device__ bf16  g_u_bf  [ROWS * DI];
__device__ bf16  g_xw64  [64 * DI];
__device__ float g_xdbl  [ROWS * 64];
__device__ float2 g_sc   [ROWS * DI];    // (delta, u) packed scan inputs (25MB)
__device__ float g_y     [ROWS * DI];
__device__ bf16  g_y_bf  [ROWS * DI];
__device__ float g_xmid  [ROWS * Cc];
__device__ bf16  g_h2_bf [ROWS * Cc];
__device__ bf16  g_m_bf  [ROWS * HID];
__device__ bf16  g_w_in  [(2 * DI) * Cc];
__device__ bf16  g_w_out [Cc * DI];
__device__ bf16  g_w_fc1 [HID * Cc];
__device__ bf16  g_w_fc2 [Cc * HID];

// ---------------- device math helpers ----------------
__device__ __forceinline__ float silu_f(float x) {
    return x / (1.0f + __expf(-x));
}
__device__ __forceinline__ float softplus_f(float x) {
    return (x > 20.0f) ? x : log1pf(expf(x));
}
__device__ __forceinline__ float gelu_f(float x) {
    // 0.5*x*(1+tanh(u)) == x*sigmoid(2u)
    float t = 1.5957691216057308f * (x + 0.044715f * x * x * x);
    return x / (1.0f + __expf(-t));
}
__device__ __forceinline__ void mma_bf16(float& c0, float& c1, float& c2, float& c3,
                                         uint32_t a0, uint32_t a1, uint32_t a2, uint32_t a3,
                                         uint32_t b0, uint32_t b1) {
    asm volatile(
        "mma.sync.aligned.m16n8k16.row.col.f32.bf16.bf16.f32 "
        "{%0,%1,%2,%3}, {%4,%5,%6,%7}, {%8,%9}, {%0,%1,%2,%3};\n"
        : "+f"(c0), "+f"(c1), "+f"(c2), "+f"(c3)
        : "r"(a0), "r"(a1), "r"(a2), "r"(a3), "r"(b0), "r"(b1));
}
__device__ __forceinline__ void ldsm_x4(uint32_t& r0, uint32_t& r1,
                                        uint32_t& r2, uint32_t& r3, uint32_t addr) {
    asm volatile("ldmatrix.sync.aligned.m8n8.x4.shared.b16 {%0,%1,%2,%3}, [%4];"
                 : "=r"(r0), "=r"(r1), "=r"(r2), "=r"(r3) : "r"(addr));
}
__device__ __forceinline__ void cp16(void* smem, const void* gmem) {
    uint32_t s = (uint32_t)__cvta_generic_to_shared(smem);
    asm volatile("cp.async.ca.shared.global [%0], [%1], 16;\n" :: "r"(s), "l"(gmem) : "memory");
}
#define CP_COMMIT() asm volatile("cp.async.commit_group;\n" ::: "memory")
#define CP_WAIT(N)  asm volatile("cp.async.wait_group %0;\n" :: "n"(N) : "memory")

// ------- weight conversion fp32 -> bf16 (4 matrices) + padded x_proj_w --------
__global__ void cvtw_kernel(const float* __restrict__ s0, bf16* __restrict__ d0, int n0,
                            const float* __restrict__ s1, bf16* __restrict__ d1, int n1,
                            const float* __restrict__ s2, bf16* __restrict__ d2, int n2,
                            const float* __restrict__ s3, bf16* __restrict__ d3, int n3,
                            const float* __restrict__ s4, bf16* __restrict__ d4) {
    int i = blockIdx.x * 256 + threadIdx.x;
    if (i < n0) d0[i] = __float2bfloat16(s0[i]);
    if (i < n1) d1[i] = __float2bfloat16(s1[i]);
    if (i < n2) d2[i] = __float2bfloat16(s2[i]);
    if (i < n3) d3[i] = __float2bfloat16(s3[i]);
    if (i < 64 * DI) {
        int r = i / DI;
        d4[i] = __float2bfloat16((r < 44) ? s4[i] : 0.f);
    }
}

// ---------------- LayerNorm (one block per row) -> bf16 out -------------------
template <int C>
__global__ void ln_kernel(const float* __restrict__ x,
                          const float* __restrict__ g,
                          const float* __restrict__ b,
                          bf16* __restrict__ out) {
    int row = blockIdx.x;
    int t   = threadIdx.x;
    float v = x[row * C + t];
    float s = v, s2 = v * v;
    __shared__ float sh[C / 32], sh2[C / 32];
#pragma unroll
    for (int o = 16; o; o >>= 1) {
        s  += __shfl_xor_sync(0xffffffffu, s,  o);
        s2 += __shfl_xor_sync(0xffffffffu, s2, o);
    }
    if ((t & 31) == 0) { sh[t >> 5] = s; sh2[t >> 5] = s2; }
    __syncthreads();
    float mean = 0.f, m2 = 0.f;
#pragma unroll
    for (int i = 0; i < C / 32; i++) { mean += sh[i]; m2 += sh2[i]; }
    mean *= (1.0f / C);
    float var = m2 * (1.0f / C) - mean * mean;
    float inv = rsqrtf(var + 1e-5f);
    out[row * C + t] = __float2bfloat16((v - mean) * inv * g[t] + b[t]);
}

// ---------------- out_norm LN + silu(z) gating -> bf16 ------------------------
__global__ void gate_ln_kernel(const float* __restrict__ y,
                               const float* __restrict__ xz,
                               const float* __restrict__ g,
                               const float* __restrict__ b,
                               bf16* __restrict__ out) {
    int row = blockIdx.x;
    int t   = threadIdx.x;           // 384
    float v = y[row * DI + t];
    float s = v, s2 = v * v;
    __shared__ float sh[DI / 32], sh2[DI / 32];
#pragma unroll
    for (int o = 16; o; o >>= 1) {
        s  += __shfl_xor_sync(0xffffffffu, s,  o);
        s2 += __shfl_xor_sync(0xffffffffu, s2, o);
    }
    if ((t & 31) == 0) { sh[t >> 5] = s; sh2[t >> 5] = s2; }
    __syncthreads();
    float mean = 0.f, m2 = 0.f;
#pragma unroll
    for (int i = 0; i < DI / 32; i++) { mean += sh[i]; m2 += sh2[i]; }
    mean *= (1.0f / DI);
    float var = m2 * (1.0f / DI) - mean * mean;
    float inv = rsqrtf(var + 1e-5f);
    float ln  = (v - mean) * inv * g[t] + b[t];
    float zz  = xz[row * (2 * DI) + DI + t];
    out[row * DI + t] = __float2bfloat16(ln * silu_f(zz));
}

// ====== bf16 mma.sync GEMM: ldmatrix + 3-stage cp.async (R8 config) ===========
#define TBM 128

template <int TBNv, int ACT, bool HAS_BIAS, bool HAS_RES, bool OUT_BF>
__global__ __launch_bounds__(256)
void gemm_bf(const bf16* __restrict__ A, int lda,
             const bf16* __restrict__ W,
             const float* __restrict__ bias,
             const float* __restrict__ res,
             float* __restrict__ Cout, bf16* __restrict__ CoutBf,
             int M, int N, int K) {
    constexpr int NW  = TBNv / 32;
    constexpr int MW  = 8 / NW;
    constexpr int ATM = TBM / (16 * MW);
    __shared__ uint32_t As[3][TBM][16];
    __shared__ uint32_t Ws[3][TBNv][16];

    int t    = threadIdx.x;
    int lane = t & 31;
    int wid  = t >> 5;
    int wm   = (wid % MW) * (ATM * 16);
    int wn   = (wid / MW) * 32;
    int gid  = lane >> 2;
    int tig  = lane & 3;
    int row0 = blockIdx.y * TBM;
    int col0 = blockIdx.x * TBNv;

    int lq  = lane & 7;
    int lh8 = (lane >> 3) & 1;
    int lk  = lane >> 4;

    uint32_t As0 = (uint32_t)__cvta_generic_to_shared(&As[0][0][0]);
    uint32_t Ws0 = (uint32_t)__cvta_generic_to_shared(&Ws[0][0][0]);

    float acc[ATM][4][4];
#pragma unroll
    for (int i = 0; i < ATM; i++)
#pragma unroll
        for (int j = 0; j < 4; j++)
#pragma unroll
            for (int q = 0; q < 4; q++) acc[i][j][q] = 0.f;

    auto stage = [&](int k0, int buf) {
#pragma unroll
        for (int i = 0; i < 2; i++) {
            int idx = t + i * 256;
            int r   = idx >> 2;
            int c   = idx & 3;
            int pc  = c ^ ((r >> 1) & 3);
            cp16(&As[buf][r][pc * 4], A + (size_t)(row0 + r) * lda + k0 + c * 8);
        }
        if (TBNv == 64) {
            int n  = t >> 2;
            int c  = t & 3;
            int pc = c ^ ((n >> 1) & 3);
            cp16(&Ws[buf][n][pc * 4], W + (size_t)(col0 + n) * K + k0 + c * 8);
        } else if (t < 128) {
            int n  = t >> 2;
            int c  = t & 3;
            int pc = c ^ ((n >> 1) & 3);
            cp16(&Ws[buf][n][pc * 4], W + (size_t)(col0 + n) * K + k0 + c * 8);
        }
    };

    int nt = K / 32;
    stage(0, 0);  CP_COMMIT();
    stage(32, 1); CP_COMMIT();

    for (int ti = 0; ti < nt; ti++) {
        if (ti + 1 < nt) { CP_WAIT(1); } else { CP_WAIT(0); }
        __syncthreads();
        if (ti + 2 < nt) { stage((ti + 2) * 32, (ti + 2) % 3); CP_COMMIT(); }

        int buf = ti % 3;
        uint32_t asb = As0 + (uint32_t)buf * (TBM * 16 * 4);
        uint32_t wsb = Ws0 + (uint32_t)buf * (TBNv * 16 * 4);

#pragma unroll
        for (int h = 0; h < 2; h++) {
            uint32_t af[ATM][4], bfr[4][2];
#pragma unroll
            for (int i = 0; i < ATM; i++) {
                int rA  = wm + i * 16 + lq + lh8 * 8;
                int chA = (2 * h + lk) ^ ((rA >> 1) & 3);
                ldsm_x4(af[i][0], af[i][1], af[i][2], af[i][3],
                        asb + (uint32_t)((rA << 4) + (chA << 2)) * 4);
            }
#pragma unroll
            for (int j2 = 0; j2 < 2; j2++) {
                int jsel = lane >> 4;
                int kc   = (lane >> 3) & 1;
                int nB   = wn + j2 * 16 + jsel * 8 + lq;
                int chB  = (2 * h + kc) ^ ((nB >> 1) & 3);
                ldsm_x4(bfr[2 * j2][0], bfr[2 * j2][1],
                        bfr[2 * j2 + 1][0], bfr[2 * j2 + 1][1],
                        wsb + (uint32_t)((nB << 4) + (chB << 2)) * 4);
            }
#pragma unroll
            for (int i = 0; i < ATM; i++)
#pragma unroll
                for (int j = 0; j < 4; j++)
                    mma_bf16(acc[i][j][0], acc[i][j][1], acc[i][j][2], acc[i][j][3],
                             af[i][0], af[i][1], af[i][2], af[i][3],
                             bfr[j][0], bfr[j][1]);
        }
    }

#pragma unroll
    for (int i = 0; i < ATM; i++) {
        int rA = row0 + wm + i * 16 + gid;
#pragma unroll
        for (int j = 0; j < 4; j++) {
            int col = col0 + wn + j * 8 + tig * 2;
            float b0 = 0.f, b1 = 0.f;
            if (HAS_BIAS) { b0 = bias[col]; b1 = bias[col + 1]; }
            float v0 = acc[i][j][0] + b0;
            float v1 = acc[i][j][1] + b1;
            float v2 = acc[i][j][2] + b0;
            float v3 = acc[i][j][3] + b1;
            if (ACT == 1) { v0 = softplus_f(v0); v1 = softplus_f(v1);
                            v2 = softplus_f(v2); v3 = softplus_f(v3); }
            else if (ACT == 2) { v0 = gelu_f(v0); v1 = gelu_f(v1);
                                 v2 = gelu_f(v2); v3 = gelu_f(v3); }
            if (HAS_RES) {
                float2 r0 = *(const float2*)&res[(size_t)rA * N + col];
                float2 r1 = *(const float2*)&res[(size_t)(rA + 8) * N + col];
                v0 += r0.x; v1 += r0.y; v2 += r1.x; v3 += r1.y;
            }
            if (OUT_BF) {
                __nv_bfloat162 p0; p0.x = __float2bfloat16(v0); p0.y = __float2bfloat16(v1);
                __nv_bfloat162 p1; p1.x = __float2bfloat16(v2); p1.y = __float2bfloat16(v3);
                *(__nv_bfloat162*)&CoutBf[(size_t)rA * N + col]       = p0;
                *(__nv_bfloat162*)&CoutBf[(size_t)(rA + 8) * N + col] = p1;
            } else {
                *(float2*)&Cout[(size_t)rA * N + col]       = make_float2(v0, v1);
                *(float2*)&Cout[(size_t)(rA + 8) * N + col] = make_float2(v2, v3);
            }
        }
    }
}

// ---------------- depthwise 3x3 conv + bias + SiLU, zigzag scatter (R8) -------
__global__ void conv_silu_kernel(const float* __restrict__ xz,
                                 const float* __restrict__ cw,
                                 const float* __restrict__ cb,
                                 const int* __restrict__ perm_rev,
                                 float* __restrict__ u,
                                 bf16* __restrict__ ubf) {
    int bp = blockIdx.x;            // b*1024 + p
    int b  = bp >> 10;
    int p  = bp & 1023;
    int h  = p >> 5;
    int w  = p & 31;
    int d  = threadIdx.x;           // 384
    float acc = cb[d];
#pragma unroll
    for (int kh = 0; kh < 3; kh++) {
        int nh = h + kh - 1;
        if ((unsigned)nh >= (unsigned)Hh) continue;
#pragma unroll
        for (int kw = 0; kw < 3; kw++) {
            int nw = w + kw - 1;
            if ((unsigned)nw >= (unsigned)Ww) continue;
            acc = fmaf(cw[d * 9 + kh * 3 + kw],
                       xz[((b << 10) + (nh << 5) + nw) * (2 * DI) + d], acc);
        }
    }
    float v = silu_f(acc);
    int o = ((b << 10) + perm_rev[p]) * DI + d;
    u[o]   = v;
    ubf[o] = __float2bfloat16(v);
}

// -------- dt_proj + softplus -> packed scan inputs (delta, u) float2 ----------
__global__ __launch_bounds__(256)
void dt_kernel(const float* __restrict__ xdbl64,  // [ROWS,64]
               const float* __restrict__ u,       // [ROWS,DI]
               const float* __restrict__ dtw,     // [384,12]
               const float* __restrict__ dtb,     // [384]
               float2* __restrict__ sc) {         // [ROWS,DI]
    __shared__ float sdt[16][13];
    int t    = threadIdx.x;
    int row0 = blockIdx.x * 16;
    if (t < 192) {
        int r = t / 12, c = t % 12;
        sdt[r][c] = xdbl64[(row0 + r) * 64 + c];
    }
    __syncthreads();
#pragma unroll
    for (int i = 0; i < 24; i++) {
        int idx = t + i * 256;
        int r   = idx / DI;
        int d   = idx % DI;
        float acc = dtb[d];
        const float* dw = &dtw[d * Rr];
#pragma unroll
        for (int j = 0; j < Rr; j++)
            acc = fmaf(sdt[r][j], dw[j], acc);
        float dl = softplus_f(acc);
        size_t o = (size_t)(row0 + r) * DI + d;
        sc[o] = make_float2(dl, u[o]);
    }
}

// ------- selective scan v2: 4 lanes x 4 states per (b,d) ----------------------
// 32-thread blocks (8 groups), 384 blocks. B/C as float4, sc broadcast.
// Per-warp: 8 groups share the same batch b -> identical B/C rows (broadcast).
__global__ __launch_bounds__(32)
void scan_kernel(const float* __restrict__ xdbl,   // [ROWS,64]
                 const float2* __restrict__ sc,    // [ROWS,DI]
                 const float* __restrict__ A_log,
                 const float* __restrict__ Dp,
                 const int* __restrict__ perm,
                 float* __restrict__ y) {
    __shared__ int sperm[Ll];
    int t = threadIdx.x;                  // 32
#pragma unroll
    for (int i = 0; i < 32; i++) sperm[t + i * 32] = perm[t + i * 32];
    __syncthreads();

    int g  = blockIdx.x * 8 + (t >> 2);   // group id: 0..3071
    int sl = t & 3;                       // lane-in-group, owns states 4sl..4sl+3
    int b  = g / DI;
    int d  = g % DI;

    float A2[4];
#pragma unroll
    for (int k = 0; k < 4; k++)
        A2[k] = -expf(A_log[d * Ss + sl * 4 + k]) * 1.4426950408889634f; // *log2e
    float Dd = Dp[d];
    float h0 = 0.f, h1 = 0.f, h2 = 0.f, h3 = 0.f;
    int base = b * Ll;

    const float2* scp = sc + (size_t)base * DI + d;
    const float*  xrow = xdbl + (size_t)base * 64;
    float* yp = y + (size_t)base * DI + d;

    // depth-4 prefetch ring
    float2 dd[4]; float4 Bv[4], Cv[4];
#pragma unroll
    for (int j = 0; j < 4; j++) {
        dd[j] = scp[(size_t)j * DI];
        Bv[j] = *(const float4*)(xrow + j * 64 + Rr + sl * 4);
        Cv[j] = *(const float4*)(xrow + j * 64 + Rr + Ss + sl * 4);
    }

    for (int l0 = 0; l0 < Ll; l0 += 4) {
#pragma unroll
        for (int j = 0; j < 4; j++) {
            int l = l0 + j;
            float dl = dd[j].x;
            float du = dl * dd[j].y;
            float uD = dd[j].y * Dd;
            h0 = fmaf(exp2f(dl * A2[0]), h0, du * Bv[j].x);
            h1 = fmaf(exp2f(dl * A2[1]), h1, du * Bv[j].y);
            h2 = fmaf(exp2f(dl * A2[2]), h2, du * Bv[j].z);
            h3 = fmaf(exp2f(dl * A2[3]), h3, du * Bv[j].w);
            float p = h0 * Cv[j].x;
            p = fmaf(h1, Cv[j].y, p);
            p = fmaf(h2, Cv[j].z, p);
            p = fmaf(h3, Cv[j].w, p);
            int ln = l + 4;
            if (ln < Ll) {
                dd[j] = scp[(size_t)ln * DI];
                Bv[j] = *(const float4*)(xrow + ln * 64 + Rr + sl * 4);
                Cv[j] = *(const float4*)(xrow + ln * 64 + Rr + Ss + sl * 4);
            }
            p += __shfl_xor_sync(0xffffffffu, p, 1, 4);
            p += __shfl_xor_sync(0xffffffffu, p, 2, 4);
            if (sl == 0) yp[(size_t)sperm[l] * DI] = p + uD;
        }
    }
}

// ---------------- launcher ----------------
extern "C" void kernel_launch(void* const* d_in, const int* in_sizes, int n_in,
                              void* d_out, int out_size) {
    const float* x          = (const float*)d_in[0];
    const int*   perm       = (const int*)  d_in[1];
    const int*   perm_rev   = (const int*)  d_in[2];
    const float* ln1_g      = (const float*)d_in[3];
    const float* ln1_b      = (const float*)d_in[4];
    const float* in_proj_w  = (const float*)d_in[5];
    const float* conv_w     = (const float*)d_in[6];
    const float* conv_b     = (const float*)d_in[7];
    const float* x_proj_w   = (const float*)d_in[8];
    const float* dt_proj_w  = (const float*)d_in[9];
    const float* dt_proj_b  = (const float*)d_in[10];
    const float* A_log      = (const float*)d_in[11];
    const float* Dp         = (const float*)d_in[12];
    const float* out_norm_g = (const float*)d_in[13];
    const float* out_norm_b = (const float*)d_in[14];
    const float* out_proj_w = (const float*)d_in[15];
    const float* ln2_g      = (const float*)d_in[16];
    const float* ln2_b      = (const float*)d_in[17];
    const float* fc1_w      = (const float*)d_in[18];
    const float* fc1_b      = (const float*)d_in[19];
    const float* fc2_w      = (const float*)d_in[20];
    const float* fc2_b      = (const float*)d_in[21];
    float* out = (float*)d_out;

    bf16 *hx, *ubf, *xw64, *ybf, *h2, *m, *w_in, *w_out, *w_fc1, *w_fc2;
    float *xz, *u, *xdbl, *y, *xmid;
    float2* sc;
    cudaGetSymbolAddress((void**)&hx,    g_hx_bf);
    cudaGetSymbolAddress((void**)&xz,    g_xz);
    cudaGetSymbolAddress((void**)&u,     g_u);
    cudaGetSymbolAddress((void**)&ubf,   g_u_bf);
    cudaGetSymbolAddress((void**)&xw64,  g_xw64);
    cudaGetSymbolAddress((void**)&xdbl,  g_xdbl);
    cudaGetSymbolAddress((void**)&sc,    g_sc);
    cudaGetSymbolAddress((void**)&y,     g_y);
    cudaGetSymbolAddress((void**)&ybf,   g_y_bf);
    cudaGetSymbolAddress((void**)&xmid,  g_xmid);
    cudaGetSymbolAddress((void**)&h2,    g_h2_bf);
    cudaGetSymbolAddress((void**)&m,     g_m_bf);
    cudaGetSymbolAddress((void**)&w_in,  g_w_in);
    cudaGetSymbolAddress((void**)&w_out, g_w_out);
    cudaGetSymbolAddress((void**)&w_fc1, g_w_fc1);
    cudaGetSymbolAddress((void**)&w_fc2, g_w_fc2);

    // 0. weights -> bf16 (incl. padded x_proj weights)
    cvtw_kernel<<<(HID * Cc + 255) / 256, 256>>>(
        in_proj_w, w_in, (2 * DI) * Cc,
        out_proj_w, w_out, Cc * DI,
        fc1_w, w_fc1, HID * Cc,
        fc2_w, w_fc2, Cc * HID,
        x_proj_w, xw64);
    // 1. LN1 -> bf16
    ln_kernel<Cc><<<ROWS, Cc>>>(x, ln1_g, ln1_b, hx);
    // 2. in_proj (TBN=64): [8192,192] x [768,192]^T -> xz fp32
    gemm_bf<64, 0, false, false, false><<<dim3((2 * DI) / 64, ROWS / TBM), 256>>>(
        hx, Cc, w_in, nullptr, nullptr, xz, nullptr, ROWS, 2 * DI, Cc);
    // 3. depthwise conv + SiLU + zigzag scatter -> u fp32 + bf16  (PROFILED)
    conv_silu_kernel<<<ROWS, DI>>>(xz, conv_w, conv_b, perm_rev, u, ubf);
    // 4. x_proj: [8192,384] x [64,384]^T -> xdbl fp32
    gemm_bf<32, 0, false, false, false><<<dim3(2, ROWS / TBM), 256>>>(
        ubf, DI, xw64, nullptr, nullptr, xdbl, nullptr, ROWS, 64, DI);
    // 5. dt_proj + softplus -> packed (delta,u) scan inputs
    dt_kernel<<<ROWS / 16, 256>>>(xdbl, u, dt_proj_w, dt_proj_b, sc);
    // 6. selective scan v2 (4 lanes x 4 states) -> y
    scan_kernel<<<(Bn * DI) / 8, 32>>>(xdbl, sc, A_log, Dp, perm, y);
    // 7. out_norm LN + silu(z) gate -> ybf
    gate_ln_kernel<<<ROWS, DI>>>(y, xz, out_norm_g, out_norm_b, ybf);
    // 8. out_proj + residual x -> xmid fp32 (TBN=32 -> 384 blocks)
    gemm_bf<32, 0, false, true, false><<<dim3(Cc / 32, ROWS / TBM), 256>>>(
        ybf, DI, w_out, nullptr, x, xmid, nullptr, ROWS, Cc, DI);
    // 9. LN2 -> bf16
    ln_kernel<Cc><<<ROWS, Cc>>>(xmid, ln2_g, ln2_b, h2);
    // 10. fc1 (TBN=64) + bias + gelu -> m bf16
    gemm_bf<64, 2, true, false, true><<<dim3(HID / 64, ROWS / TBM), 256>>>(
        h2, Cc, w_fc1, fc1_b, nullptr, nullptr, m, ROWS, HID, Cc);
    // 11. fc2 + bias + residual xmid -> out fp32 (TBN=32 -> 384 blocks)
    gemm_bf<32, 0, true, true, false><<<dim3(Cc / 32, ROWS / TBM), 256>>>(
        m, HID, w_fc2, fc2_b, xmid, out, nullptr, ROWS, Cc, HID);
}

// round 15
// speedup vs baseline: 1.2975x; 1.2975x over previous
#include <cuda_runtime.h>
#include <cuda_bf16.h>
#include <math.h>
#include <stdint.h>

// Problem constants
#define Bn   8
#define Hh   32
#define Ww   32
#define Cc   192
#define DI   384
#define Ss   16
#define Rr   12
#define HID  768
#define Ll   1024          // H*W
#define ROWS (Bn * Ll)     // 8192

typedef __nv_bfloat16 bf16;

// ---------------- scratch (no allocation allowed) ----------------
__device__ bf16  g_hx_bf [ROWS * Cc];
__device__ float g_xz    [ROWS * (2 * DI)];
__device__ float g_u     [ROWS * DI];
__device__ bf16  g_u_bf  [ROWS * DI];
__device__ bf16  g_xw64  [64 * DI];
__device__ float g_xdbl  [ROWS * 64];
__device__ float2 g_sc   [ROWS * DI];    // (delta, u) packed scan inputs (25MB)
__device__ float g_y     [ROWS * DI];
__device__ bf16  g_y_bf  [ROWS * DI];
__device__ float g_xmid  [ROWS * Cc];
__device__ bf16  g_h2_bf [ROWS * Cc];
__device__ bf16  g_m_bf  [ROWS * HID];
__device__ bf16  g_w_in  [(2 * DI) * Cc];
__device__ bf16  g_w_out [Cc * DI];
__device__ bf16  g_w_fc1 [HID * Cc];
__device__ bf16  g_w_fc2 [Cc * HID];

// ---------------- device math helpers ----------------
__device__ __forceinline__ float silu_f(float x) {
    return x / (1.0f + __expf(-x));
}
__device__ __forceinline__ float softplus_f(float x) {
    return (x > 20.0f) ? x : log1pf(expf(x));
}
__device__ __forceinline__ float gelu_f(float x) {
    // 0.5*x*(1+tanh(u)) == x*sigmoid(2u)
    float t = 1.5957691216057308f * (x + 0.044715f * x * x * x);
    return x / (1.0f + __expf(-t));
}
__device__ __forceinline__ void mma_bf16(float& c0, float& c1, float& c2, float& c3,
                                         uint32_t a0, uint32_t a1, uint32_t a2, uint32_t a3,
                                         uint32_t b0, uint32_t b1) {
    asm volatile(
        "mma.sync.aligned.m16n8k16.row.col.f32.bf16.bf16.f32 "
        "{%0,%1,%2,%3}, {%4,%5,%6,%7}, {%8,%9}, {%0,%1,%2,%3};\n"
        : "+f"(c0), "+f"(c1), "+f"(c2), "+f"(c3)
        : "r"(a0), "r"(a1), "r"(a2), "r"(a3), "r"(b0), "r"(b1));
}
__device__ __forceinline__ void ldsm_x4(uint32_t& r0, uint32_t& r1,
                                        uint32_t& r2, uint32_t& r3, uint32_t addr) {
    asm volatile("ldmatrix.sync.aligned.m8n8.x4.shared.b16 {%0,%1,%2,%3}, [%4];"
                 : "=r"(r0), "=r"(r1), "=r"(r2), "=r"(r3) : "r"(addr));
}
__device__ __forceinline__ void cp16(void* smem, const void* gmem) {
    uint32_t s = (uint32_t)__cvta_generic_to_shared(smem);
    asm volatile("cp.async.ca.shared.global [%0], [%1], 16;\n" :: "r"(s), "l"(gmem) : "memory");
}
#define CP_COMMIT() asm volatile("cp.async.commit_group;\n" ::: "memory")
#define CP_WAIT(N)  asm volatile("cp.async.wait_group %0;\n" :: "n"(N) : "memory")

// ------- weight conversion fp32 -> bf16 (4 matrices) + padded x_proj_w --------
__global__ void cvtw_kernel(const float* __restrict__ s0, bf16* __restrict__ d0, int n0,
                            const float* __restrict__ s1, bf16* __restrict__ d1, int n1,
                            const float* __restrict__ s2, bf16* __restrict__ d2, int n2,
                            const float* __restrict__ s3, bf16* __restrict__ d3, int n3,
                            const float* __restrict__ s4, bf16* __restrict__ d4) {
    int i = blockIdx.x * 256 + threadIdx.x;
    if (i < n0) d0[i] = __float2bfloat16(s0[i]);
    if (i < n1) d1[i] = __float2bfloat16(s1[i]);
    if (i < n2) d2[i] = __float2bfloat16(s2[i]);
    if (i < n3) d3[i] = __float2bfloat16(s3[i]);
    if (i < 64 * DI) {
        int r = i / DI;
        d4[i] = __float2bfloat16((r < 44) ? s4[i] : 0.f);
    }
}

// ---------------- LayerNorm (one block per row) -> bf16 out -------------------
template <int C>
__global__ void ln_kernel(const float* __restrict__ x,
                          const float* __restrict__ g,
                          const float* __restrict__ b,
                          bf16* __restrict__ out) {
    int row = blockIdx.x;
    int t   = threadIdx.x;
    float v = x[row * C + t];
    float s = v, s2 = v * v;
    __shared__ float sh[C / 32], sh2[C / 32];
#pragma unroll
    for (int o = 16; o; o >>= 1) {
        s  += __shfl_xor_sync(0xffffffffu, s,  o);
        s2 += __shfl_xor_sync(0xffffffffu, s2, o);
    }
    if ((t & 31) == 0) { sh[t >> 5] = s; sh2[t >> 5] = s2; }
    __syncthreads();
    float mean = 0.f, m2 = 0.f;
#pragma unroll
    for (int i = 0; i < C / 32; i++) { mean += sh[i]; m2 += sh2[i]; }
    mean *= (1.0f / C);
    float var = m2 * (1.0f / C) - mean * mean;
    float inv = rsqrtf(var + 1e-5f);
    out[row * C + t] = __float2bfloat16((v - mean) * inv * g[t] + b[t]);
}

// ---------------- out_norm LN + silu(z) gating -> bf16 ------------------------
__global__ void gate_ln_kernel(const float* __restrict__ y,
                               const float* __restrict__ xz,
                               const float* __restrict__ g,
                               const float* __restrict__ b,
                               bf16* __restrict__ out) {
    int row = blockIdx.x;
    int t   = threadIdx.x;           // 384
    float v = y[row * DI + t];
    float s = v, s2 = v * v;
    __shared__ float sh[DI / 32], sh2[DI / 32];
#pragma unroll
    for (int o = 16; o; o >>= 1) {
        s  += __shfl_xor_sync(0xffffffffu, s,  o);
        s2 += __shfl_xor_sync(0xffffffffu, s2, o);
    }
    if ((t & 31) == 0) { sh[t >> 5] = s; sh2[t >> 5] = s2; }
    __syncthreads();
    float mean = 0.f, m2 = 0.f;
#pragma unroll
    for (int i = 0; i < DI / 32; i++) { mean += sh[i]; m2 += sh2[i]; }
    mean *= (1.0f / DI);
    float var = m2 * (1.0f / DI) - mean * mean;
    float inv = rsqrtf(var + 1e-5f);
    float ln  = (v - mean) * inv * g[t] + b[t];
    float zz  = xz[row * (2 * DI) + DI + t];
    out[row * DI + t] = __float2bfloat16(ln * silu_f(zz));
}

// ====== bf16 mma.sync GEMM: ldmatrix + 3-stage cp.async (R8 config) ===========
#define TBM 128

template <int TBNv, int ACT, bool HAS_BIAS, bool HAS_RES, bool OUT_BF>
__global__ __launch_bounds__(256)
void gemm_bf(const bf16* __restrict__ A, int lda,
             const bf16* __restrict__ W,
             const float* __restrict__ bias,
             const float* __restrict__ res,
             float* __restrict__ Cout, bf16* __restrict__ CoutBf,
             int M, int N, int K) {
    constexpr int NW  = TBNv / 32;
    constexpr int MW  = 8 / NW;
    constexpr int ATM = TBM / (16 * MW);
    __shared__ uint32_t As[3][TBM][16];
    __shared__ uint32_t Ws[3][TBNv][16];

    int t    = threadIdx.x;
    int lane = t & 31;
    int wid  = t >> 5;
    int wm   = (wid % MW) * (ATM * 16);
    int wn   = (wid / MW) * 32;
    int gid  = lane >> 2;
    int tig  = lane & 3;
    int row0 = blockIdx.y * TBM;
    int col0 = blockIdx.x * TBNv;

    int lq  = lane & 7;
    int lh8 = (lane >> 3) & 1;
    int lk  = lane >> 4;

    uint32_t As0 = (uint32_t)__cvta_generic_to_shared(&As[0][0][0]);
    uint32_t Ws0 = (uint32_t)__cvta_generic_to_shared(&Ws[0][0][0]);

    float acc[ATM][4][4];
#pragma unroll
    for (int i = 0; i < ATM; i++)
#pragma unroll
        for (int j = 0; j < 4; j++)
#pragma unroll
            for (int q = 0; q < 4; q++) acc[i][j][q] = 0.f;

    auto stage = [&](int k0, int buf) {
#pragma unroll
        for (int i = 0; i < 2; i++) {
            int idx = t + i * 256;
            int r   = idx >> 2;
            int c   = idx & 3;
            int pc  = c ^ ((r >> 1) & 3);
            cp16(&As[buf][r][pc * 4], A + (size_t)(row0 + r) * lda + k0 + c * 8);
        }
        if (TBNv == 64) {
            int n  = t >> 2;
            int c  = t & 3;
            int pc = c ^ ((n >> 1) & 3);
            cp16(&Ws[buf][n][pc * 4], W + (size_t)(col0 + n) * K + k0 + c * 8);
        } else if (t < 128) {
            int n  = t >> 2;
            int c  = t & 3;
            int pc = c ^ ((n >> 1) & 3);
            cp16(&Ws[buf][n][pc * 4], W + (size_t)(col0 + n) * K + k0 + c * 8);
        }
    };

    int nt = K / 32;
    stage(0, 0);  CP_COMMIT();
    stage(32, 1); CP_COMMIT();

    for (int ti = 0; ti < nt; ti++) {
        if (ti + 1 < nt) { CP_WAIT(1); } else { CP_WAIT(0); }
        __syncthreads();
        if (ti + 2 < nt) { stage((ti + 2) * 32, (ti + 2) % 3); CP_COMMIT(); }

        int buf = ti % 3;
        uint32_t asb = As0 + (uint32_t)buf * (TBM * 16 * 4);
        uint32_t wsb = Ws0 + (uint32_t)buf * (TBNv * 16 * 4);

#pragma unroll
        for (int h = 0; h < 2; h++) {
            uint32_t af[ATM][4], bfr[4][2];
#pragma unroll
            for (int i = 0; i < ATM; i++) {
                int rA  = wm + i * 16 + lq + lh8 * 8;
                int chA = (2 * h + lk) ^ ((rA >> 1) & 3);
                ldsm_x4(af[i][0], af[i][1], af[i][2], af[i][3],
                        asb + (uint32_t)((rA << 4) + (chA << 2)) * 4);
            }
#pragma unroll
            for (int j2 = 0; j2 < 2; j2++) {
                int jsel = lane >> 4;
                int kc   = (lane >> 3) & 1;
                int nB   = wn + j2 * 16 + jsel * 8 + lq;
                int chB  = (2 * h + kc) ^ ((nB >> 1) & 3);
                ldsm_x4(bfr[2 * j2][0], bfr[2 * j2][1],
                        bfr[2 * j2 + 1][0], bfr[2 * j2 + 1][1],
                        wsb + (uint32_t)((nB << 4) + (chB << 2)) * 4);
            }
#pragma unroll
            for (int i = 0; i < ATM; i++)
#pragma unroll
                for (int j = 0; j < 4; j++)
                    mma_bf16(acc[i][j][0], acc[i][j][1], acc[i][j][2], acc[i][j][3],
                             af[i][0], af[i][1], af[i][2], af[i][3],
                             bfr[j][0], bfr[j][1]);
        }
    }

#pragma unroll
    for (int i = 0; i < ATM; i++) {
        int rA = row0 + wm + i * 16 + gid;
#pragma unroll
        for (int j = 0; j < 4; j++) {
            int col = col0 + wn + j * 8 + tig * 2;
            float b0 = 0.f, b1 = 0.f;
            if (HAS_BIAS) { b0 = bias[col]; b1 = bias[col + 1]; }
            float v0 = acc[i][j][0] + b0;
            float v1 = acc[i][j][1] + b1;
            float v2 = acc[i][j][2] + b0;
            float v3 = acc[i][j][3] + b1;
            if (ACT == 1) { v0 = softplus_f(v0); v1 = softplus_f(v1);
                            v2 = softplus_f(v2); v3 = softplus_f(v3); }
            else if (ACT == 2) { v0 = gelu_f(v0); v1 = gelu_f(v1);
                                 v2 = gelu_f(v2); v3 = gelu_f(v3); }
            if (HAS_RES) {
                float2 r0 = *(const float2*)&res[(size_t)rA * N + col];
                float2 r1 = *(const float2*)&res[(size_t)(rA + 8) * N + col];
                v0 += r0.x; v1 += r0.y; v2 += r1.x; v3 += r1.y;
            }
            if (OUT_BF) {
                __nv_bfloat162 p0; p0.x = __float2bfloat16(v0); p0.y = __float2bfloat16(v1);
                __nv_bfloat162 p1; p1.x = __float2bfloat16(v2); p1.y = __float2bfloat16(v3);
                *(__nv_bfloat162*)&CoutBf[(size_t)rA * N + col]       = p0;
                *(__nv_bfloat162*)&CoutBf[(size_t)(rA + 8) * N + col] = p1;
            } else {
                *(float2*)&Cout[(size_t)rA * N + col]       = make_float2(v0, v1);
                *(float2*)&Cout[(size_t)(rA + 8) * N + col] = make_float2(v2, v3);
            }
        }
    }
}

// ---------------- depthwise 3x3 conv + bias + SiLU, zigzag scatter (R8) -------
__global__ void conv_silu_kernel(const float* __restrict__ xz,
                                 const float* __restrict__ cw,
                                 const float* __restrict__ cb,
                                 const int* __restrict__ perm_rev,
                                 float* __restrict__ u,
                                 bf16* __restrict__ ubf) {
    int bp = blockIdx.x;            // b*1024 + p
    int b  = bp >> 10;
    int p  = bp & 1023;
    int h  = p >> 5;
    int w  = p & 31;
    int d  = threadIdx.x;           // 384
    float acc = cb[d];
#pragma unroll
    for (int kh = 0; kh < 3; kh++) {
        int nh = h + kh - 1;
        if ((unsigned)nh >= (unsigned)Hh) continue;
#pragma unroll
        for (int kw = 0; kw < 3; kw++) {
            int nw = w + kw - 1;
            if ((unsigned)nw >= (unsigned)Ww) continue;
            acc = fmaf(cw[d * 9 + kh * 3 + kw],
                       xz[((b << 10) + (nh << 5) + nw) * (2 * DI) + d], acc);
        }
    }
    float v = silu_f(acc);
    int o = ((b << 10) + perm_rev[p]) * DI + d;
    u[o]   = v;
    ubf[o] = __float2bfloat16(v);
}

// -------- dt_proj + softplus -> packed scan inputs (delta, u) float2 ----------
__global__ __launch_bounds__(256)
void dt_kernel(const float* __restrict__ xdbl64,  // [ROWS,64]
               const float* __restrict__ u,       // [ROWS,DI]
               const float* __restrict__ dtw,     // [384,12]
               const float* __restrict__ dtb,     // [384]
               float2* __restrict__ sc) {         // [ROWS,DI]
    __shared__ float sdt[16][13];
    int t    = threadIdx.x;
    int row0 = blockIdx.x * 16;
    if (t < 192) {
        int r = t / 12, c = t % 12;
        sdt[r][c] = xdbl64[(row0 + r) * 64 + c];
    }
    __syncthreads();
#pragma unroll
    for (int i = 0; i < 24; i++) {
        int idx = t + i * 256;
        int r   = idx / DI;
        int d   = idx % DI;
        float acc = dtb[d];
        const float* dw = &dtw[d * Rr];
#pragma unroll
        for (int j = 0; j < Rr; j++)
            acc = fmaf(sdt[r][j], dw[j], acc);
        float dl = softplus_f(acc);
        size_t o = (size_t)(row0 + r) * DI + d;
        sc[o] = make_float2(dl, u[o]);
    }
}

// ------- selective scan v3: 4 lanes x 4 states, depth-8 prefetch ring ---------
// 32-thread blocks (8 groups), 384 blocks. B/C float4 (warp-broadcast rows).
// Ring depth 8 covers ~L2 latency (sc stays L2-resident after dt_kernel).
__global__ __launch_bounds__(32)
void scan_kernel(const float* __restrict__ xdbl,   // [ROWS,64]
                 const float2* __restrict__ sc,    // [ROWS,DI]
                 const float* __restrict__ A_log,
                 const float* __restrict__ Dp,
                 const int* __restrict__ perm,
                 float* __restrict__ y) {
    __shared__ int sperm[Ll];
    int t = threadIdx.x;                  // 32
#pragma unroll
    for (int i = 0; i < 32; i++) sperm[t + i * 32] = perm[t + i * 32];
    __syncwarp();

    int g  = blockIdx.x * 8 + (t >> 2);   // group id: 0..3071
    int sl = t & 3;                       // lane-in-group, owns states 4sl..4sl+3
    int b  = g / DI;
    int d  = g % DI;

    float A2[4];
#pragma unroll
    for (int k = 0; k < 4; k++)
        A2[k] = -expf(A_log[d * Ss + sl * 4 + k]) * 1.4426950408889634f; // *log2e
    float Dd = Dp[d];
    float h0 = 0.f, h1 = 0.f, h2 = 0.f, h3 = 0.f;
    int base = b * Ll;

    const float2* scp = sc + (size_t)base * DI + d;
    const float*  xrow = xdbl + (size_t)base * 64;
    float* yp = y + (size_t)base * DI + d;

    // depth-8 prefetch ring
    float2 dd[8]; float4 Bv[8], Cv[8];
#pragma unroll
    for (int j = 0; j < 8; j++) {
        dd[j] = scp[(size_t)j * DI];
        Bv[j] = *(const float4*)(xrow + j * 64 + Rr + sl * 4);
        Cv[j] = *(const float4*)(xrow + j * 64 + Rr + Ss + sl * 4);
    }

    for (int l0 = 0; l0 < Ll; l0 += 8) {
#pragma unroll
        for (int j = 0; j < 8; j++) {
            int l = l0 + j;
            float dl = dd[j].x;
            float du = dl * dd[j].y;
            float uD = dd[j].y * Dd;
            h0 = fmaf(exp2f(dl * A2[0]), h0, du * Bv[j].x);
            h1 = fmaf(exp2f(dl * A2[1]), h1, du * Bv[j].y);
            h2 = fmaf(exp2f(dl * A2[2]), h2, du * Bv[j].z);
            h3 = fmaf(exp2f(dl * A2[3]), h3, du * Bv[j].w);
            float p = h0 * Cv[j].x;
            p = fmaf(h1, Cv[j].y, p);
            p = fmaf(h2, Cv[j].z, p);
            p = fmaf(h3, Cv[j].w, p);
            int ln = l + 8;
            if (ln < Ll) {
                dd[j] = scp[(size_t)ln * DI];
                Bv[j] = *(const float4*)(xrow + ln * 64 + Rr + sl * 4);
                Cv[j] = *(const float4*)(xrow + ln * 64 + Rr + Ss + sl * 4);
            }
            p += __shfl_xor_sync(0xffffffffu, p, 1, 4);
            p += __shfl_xor_sync(0xffffffffu, p, 2, 4);
            if (sl == 0) yp[(size_t)sperm[l] * DI] = p + uD;
        }
    }
}

// ---------------- launcher ----------------
extern "C" void kernel_launch(void* const* d_in, const int* in_sizes, int n_in,
                              void* d_out, int out_size) {
    const float* x          = (const float*)d_in[0];
    const int*   perm       = (const int*)  d_in[1];
    const int*   perm_rev   = (const int*)  d_in[2];
    const float* ln1_g      = (const float*)d_in[3];
    const float* ln1_b      = (const float*)d_in[4];
    const float* in_proj_w  = (const float*)d_in[5];
    const float* conv_w     = (const float*)d_in[6];
    const float* conv_b     = (const float*)d_in[7];
    const float* x_proj_w   = (const float*)d_in[8];
    const float* dt_proj_w  = (const float*)d_in[9];
    const float* dt_proj_b  = (const float*)d_in[10];
    const float* A_log      = (const float*)d_in[11];
    const float* Dp         = (const float*)d_in[12];
    const float* out_norm_g = (const float*)d_in[13];
    const float* out_norm_b = (const float*)d_in[14];
    const float* out_proj_w = (const float*)d_in[15];
    const float* ln2_g      = (const float*)d_in[16];
    const float* ln2_b      = (const float*)d_in[17];
    const float* fc1_w      = (const float*)d_in[18];
    const float* fc1_b      = (const float*)d_in[19];
    const float* fc2_w      = (const float*)d_in[20];
    const float* fc2_b      = (const float*)d_in[21];
    float* out = (float*)d_out;

    bf16 *hx, *ubf, *xw64, *ybf, *h2, *m, *w_in, *w_out, *w_fc1, *w_fc2;
    float *xz, *u, *xdbl, *y, *xmid;
    float2* sc;
    cudaGetSymbolAddress((void**)&hx,    g_hx_bf);
    cudaGetSymbolAddress((void**)&xz,    g_xz);
    cudaGetSymbolAddress((void**)&u,     g_u);
    cudaGetSymbolAddress((void**)&ubf,   g_u_bf);
    cudaGetSymbolAddress((void**)&xw64,  g_xw64);
    cudaGetSymbolAddress((void**)&xdbl,  g_xdbl);
    cudaGetSymbolAddress((void**)&sc,    g_sc);
    cudaGetSymbolAddress((void**)&y,     g_y);
    cudaGetSymbolAddress((void**)&ybf,   g_y_bf);
    cudaGetSymbolAddress((void**)&xmid,  g_xmid);
    cudaGetSymbolAddress((void**)&h2,    g_h2_bf);
    cudaGetSymbolAddress((void**)&m,     g_m_bf);
    cudaGetSymbolAddress((void**)&w_in,  g_w_in);
    cudaGetSymbolAddress((void**)&w_out, g_w_out);
    cudaGetSymbolAddress((void**)&w_fc1, g_w_fc1);
    cudaGetSymbolAddress((void**)&w_fc2, g_w_fc2);

    // 0. weights -> bf16 (incl. padded x_proj weights)
    cvtw_kernel<<<(HID * Cc + 255) / 256, 256>>>(
        in_proj_w, w_in, (2 * DI) * Cc,
        out_proj_w, w_out, Cc * DI,
        fc1_w, w_fc1, HID * Cc,
        fc2_w, w_fc2, Cc * HID,
        x_proj_w, xw64);
    // 1. LN1 -> bf16
    ln_kernel<Cc><<<ROWS, Cc>>>(x, ln1_g, ln1_b, hx);
    // 2. in_proj (TBN=64): [8192,192] x [768,192]^T -> xz fp32
    gemm_bf<64, 0, false, false, false><<<dim3((2 * DI) / 64, ROWS / TBM), 256>>>(
        hx, Cc, w_in, nullptr, nullptr, xz, nullptr, ROWS, 2 * DI, Cc);
    // 3. depthwise conv + SiLU + zigzag scatter -> u fp32 + bf16
    conv_silu_kernel<<<ROWS, DI>>>(xz, conv_w, conv_b, perm_rev, u, ubf);
    // 4. x_proj: [8192,384] x [64,384]^T -> xdbl fp32
    gemm_bf<32, 0, false, false, false><<<dim3(2, ROWS / TBM), 256>>>(
        ubf, DI, xw64, nullptr, nullptr, xdbl, nullptr, ROWS, 64, DI);
    // 5. dt_proj + softplus -> packed (delta,u) scan inputs
    dt_kernel<<<ROWS / 16, 256>>>(xdbl, u, dt_proj_w, dt_proj_b, sc);
    // 6. selective scan v3 (4x4, depth-8 ring) -> y
    scan_kernel<<<(Bn * DI) / 8, 32>>>(xdbl, sc, A_log, Dp, perm, y);
    // 7. out_norm LN + silu(z) gate -> ybf
    gate_ln_kernel<<<ROWS, DI>>>(y, xz, out_norm_g, out_norm_b, ybf);
    // 8. out_proj + residual x -> xmid fp32 (TBN=32 -> 384 blocks)
    gemm_bf<32, 0, false, true, false><<<dim3(Cc / 32, ROWS / TBM), 256>>>(
        ybf, DI, w_out, nullptr, x, xmid, nullptr, ROWS, Cc, DI);
    // 9. LN2 -> bf16
    ln_kernel<Cc><<<ROWS, Cc>>>(xmid, ln2_g, ln2_b, h2);
    // 10. fc1 (TBN=64) + bias + gelu -> m bf16
    gemm_bf<64, 2, true, false, true><<<dim3(HID / 64, ROWS / TBM), 256>>>(
        h2, Cc, w_fc1, fc1_b, nullptr, nullptr, m, ROWS, HID, Cc);
    // 11. fc2 + bias + residual xmid -> out fp32 (TBN=32 -> 384 blocks)
    gemm_bf<32, 0, true, true, false><<<dim3(Cc / 32, ROWS / TBM), 256>>>(
        m, HID, w_fc2, fc2_b, xmid, out, nullptr, ROWS, Cc, HID);
}

// round 17
// speedup vs baseline: 1.3283x; 1.0238x over previous
#include <cuda_runtime.h>
#include <cuda_bf16.h>
#include <math.h>
#include <stdint.h>

// Problem constants
#define Bn   8
#define Hh   32
#define Ww   32
#define Cc   192
#define DI   384
#define Ss   16
#define Rr   12
#define HID  768
#define Ll   1024          // H*W
#define ROWS (Bn * Ll)     // 8192

typedef __nv_bfloat16 bf16;

// ---------------- scratch (no allocation allowed) ----------------
__device__ bf16  g_hx_bf [ROWS * Cc];
__device__ float g_xz    [ROWS * (2 * DI)];
__device__ float g_u     [ROWS * DI];
__device__ bf16  g_u_bf  [ROWS * DI];
__device__ bf16  g_xw64  [64 * DI];
__device__ float g_xdbl  [ROWS * 64];
__device__ float2 g_sc   [ROWS * DI];    // (delta, u) packed scan inputs (25MB)
__device__ float g_y     [ROWS * DI];
__device__ bf16  g_y_bf  [ROWS * DI];
__device__ float g_xmid  [ROWS * Cc];
__device__ bf16  g_h2_bf [ROWS * Cc];
__device__ bf16  g_m_bf  [ROWS * HID];
__device__ bf16  g_w_in  [(2 * DI) * Cc];
__device__ bf16  g_w_out [Cc * DI];
__device__ bf16  g_w_fc1 [HID * Cc];
__device__ bf16  g_w_fc2 [Cc * HID];

// ---------------- device math helpers ----------------
__device__ __forceinline__ float silu_f(float x) {
    return x / (1.0f + __expf(-x));
}
__device__ __forceinline__ float softplus_f(float x) {
    return (x > 20.0f) ? x : log1pf(expf(x));
}
__device__ __forceinline__ float gelu_f(float x) {
    // 0.5*x*(1+tanh(u)) == x*sigmoid(2u)
    float t = 1.5957691216057308f * (x + 0.044715f * x * x * x);
    return x / (1.0f + __expf(-t));
}
__device__ __forceinline__ void mma_bf16(float& c0, float& c1, float& c2, float& c3,
                                         uint32_t a0, uint32_t a1, uint32_t a2, uint32_t a3,
                                         uint32_t b0, uint32_t b1) {
    asm volatile(
        "mma.sync.aligned.m16n8k16.row.col.f32.bf16.bf16.f32 "
        "{%0,%1,%2,%3}, {%4,%5,%6,%7}, {%8,%9}, {%0,%1,%2,%3};\n"
        : "+f"(c0), "+f"(c1), "+f"(c2), "+f"(c3)
        : "r"(a0), "r"(a1), "r"(a2), "r"(a3), "r"(b0), "r"(b1));
}
__device__ __forceinline__ void ldsm_x4(uint32_t& r0, uint32_t& r1,
                                        uint32_t& r2, uint32_t& r3, uint32_t addr) {
    asm volatile("ldmatrix.sync.aligned.m8n8.x4.shared.b16 {%0,%1,%2,%3}, [%4];"
                 : "=r"(r0), "=r"(r1), "=r"(r2), "=r"(r3) : "r"(addr));
}
__device__ __forceinline__ void cp16(void* smem, const void* gmem) {
    uint32_t s = (uint32_t)__cvta_generic_to_shared(smem);
    asm volatile("cp.async.ca.shared.global [%0], [%1], 16;\n" :: "r"(s), "l"(gmem) : "memory");
}
#define CP_COMMIT() asm volatile("cp.async.commit_group;\n" ::: "memory")
#define CP_WAIT(N)  asm volatile("cp.async.wait_group %0;\n" :: "n"(N) : "memory")

// ------- weight conversion fp32 -> bf16 (4 matrices) + padded x_proj_w --------
__global__ void cvtw_kernel(const float* __restrict__ s0, bf16* __restrict__ d0, int n0,
                            const float* __restrict__ s1, bf16* __restrict__ d1, int n1,
                            const float* __restrict__ s2, bf16* __restrict__ d2, int n2,
                            const float* __restrict__ s3, bf16* __restrict__ d3, int n3,
                            const float* __restrict__ s4, bf16* __restrict__ d4) {
    int i = blockIdx.x * 256 + threadIdx.x;
    if (i < n0) d0[i] = __float2bfloat16(s0[i]);
    if (i < n1) d1[i] = __float2bfloat16(s1[i]);
    if (i < n2) d2[i] = __float2bfloat16(s2[i]);
    if (i < n3) d3[i] = __float2bfloat16(s3[i]);
    if (i < 64 * DI) {
        int r = i / DI;
        d4[i] = __float2bfloat16((r < 44) ? s4[i] : 0.f);
    }
}

// ---------------- LayerNorm (one block per row) -> bf16 out -------------------
template <int C>
__global__ void ln_kernel(const float* __restrict__ x,
                          const float* __restrict__ g,
                          const float* __restrict__ b,
                          bf16* __restrict__ out) {
    int row = blockIdx.x;
    int t   = threadIdx.x;
    float v = x[row * C + t];
    float s = v, s2 = v * v;
    __shared__ float sh[C / 32], sh2[C / 32];
#pragma unroll
    for (int o = 16; o; o >>= 1) {
        s  += __shfl_xor_sync(0xffffffffu, s,  o);
        s2 += __shfl_xor_sync(0xffffffffu, s2, o);
    }
    if ((t & 31) == 0) { sh[t >> 5] = s; sh2[t >> 5] = s2; }
    __syncthreads();
    float mean = 0.f, m2 = 0.f;
#pragma unroll
    for (int i = 0; i < C / 32; i++) { mean += sh[i]; m2 += sh2[i]; }
    mean *= (1.0f / C);
    float var = m2 * (1.0f / C) - mean * mean;
    float inv = rsqrtf(var + 1e-5f);
    out[row * C + t] = __float2bfloat16((v - mean) * inv * g[t] + b[t]);
}

// ---------------- out_norm LN + silu(z) gating -> bf16 ------------------------
__global__ void gate_ln_kernel(const float* __restrict__ y,
                               const float* __restrict__ xz,
                               const float* __restrict__ g,
                               const float* __restrict__ b,
                               bf16* __restrict__ out) {
    int row = blockIdx.x;
    int t   = threadIdx.x;           // 384
    float v = y[row * DI + t];
    float s = v, s2 = v * v;
    __shared__ float sh[DI / 32], sh2[DI / 32];
#pragma unroll
    for (int o = 16; o; o >>= 1) {
        s  += __shfl_xor_sync(0xffffffffu, s,  o);
        s2 += __shfl_xor_sync(0xffffffffu, s2, o);
    }
    if ((t & 31) == 0) { sh[t >> 5] = s; sh2[t >> 5] = s2; }
    __syncthreads();
    float mean = 0.f, m2 = 0.f;
#pragma unroll
    for (int i = 0; i < DI / 32; i++) { mean += sh[i]; m2 += sh2[i]; }
    mean *= (1.0f / DI);
    float var = m2 * (1.0f / DI) - mean * mean;
    float inv = rsqrtf(var + 1e-5f);
    float ln  = (v - mean) * inv * g[t] + b[t];
    float zz  = xz[row * (2 * DI) + DI + t];
    out[row * DI + t] = __float2bfloat16(ln * silu_f(zz));
}

// ====== bf16 mma.sync GEMM: ldmatrix + 3-stage cp.async (R8 config) ===========
#define TBM 128

template <int TBNv, int ACT, bool HAS_BIAS, bool HAS_RES, bool OUT_BF>
__global__ __launch_bounds__(256)
void gemm_bf(const bf16* __restrict__ A, int lda,
             const bf16* __restrict__ W,
             const float* __restrict__ bias,
             const float* __restrict__ res,
             float* __restrict__ Cout, bf16* __restrict__ CoutBf,
             int M, int N, int K) {
    constexpr int NW  = TBNv / 32;
    constexpr int MW  = 8 / NW;
    constexpr int ATM = TBM / (16 * MW);
    __shared__ uint32_t As[3][TBM][16];
    __shared__ uint32_t Ws[3][TBNv][16];

    int t    = threadIdx.x;
    int lane = t & 31;
    int wid  = t >> 5;
    int wm   = (wid % MW) * (ATM * 16);
    int wn   = (wid / MW) * 32;
    int gid  = lane >> 2;
    int tig  = lane & 3;
    int row0 = blockIdx.y * TBM;
    int col0 = blockIdx.x * TBNv;

    int lq  = lane & 7;
    int lh8 = (lane >> 3) & 1;
    int lk  = lane >> 4;

    uint32_t As0 = (uint32_t)__cvta_generic_to_shared(&As[0][0][0]);
    uint32_t Ws0 = (uint32_t)__cvta_generic_to_shared(&Ws[0][0][0]);

    float acc[ATM][4][4];
#pragma unroll
    for (int i = 0; i < ATM; i++)
#pragma unroll
        for (int j = 0; j < 4; j++)
#pragma unroll
            for (int q = 0; q < 4; q++) acc[i][j][q] = 0.f;

    auto stage = [&](int k0, int buf) {
#pragma unroll
        for (int i = 0; i < 2; i++) {
            int idx = t + i * 256;
            int r   = idx >> 2;
            int c   = idx & 3;
            int pc  = c ^ ((r >> 1) & 3);
            cp16(&As[buf][r][pc * 4], A + (size_t)(row0 + r) * lda + k0 + c * 8);
        }
        if (TBNv == 64) {
            int n  = t >> 2;
            int c  = t & 3;
            int pc = c ^ ((n >> 1) & 3);
            cp16(&Ws[buf][n][pc * 4], W + (size_t)(col0 + n) * K + k0 + c * 8);
        } else if (t < 128) {
            int n  = t >> 2;
            int c  = t & 3;
            int pc = c ^ ((n >> 1) & 3);
            cp16(&Ws[buf][n][pc * 4], W + (size_t)(col0 + n) * K + k0 + c * 8);
        }
    };

    int nt = K / 32;
    stage(0, 0);  CP_COMMIT();
    stage(32, 1); CP_COMMIT();

    for (int ti = 0; ti < nt; ti++) {
        if (ti + 1 < nt) { CP_WAIT(1); } else { CP_WAIT(0); }
        __syncthreads();
        if (ti + 2 < nt) { stage((ti + 2) * 32, (ti + 2) % 3); CP_COMMIT(); }

        int buf = ti % 3;
        uint32_t asb = As0 + (uint32_t)buf * (TBM * 16 * 4);
        uint32_t wsb = Ws0 + (uint32_t)buf * (TBNv * 16 * 4);

#pragma unroll
        for (int h = 0; h < 2; h++) {
            uint32_t af[ATM][4], bfr[4][2];
#pragma unroll
            for (int i = 0; i < ATM; i++) {
                int rA  = wm + i * 16 + lq + lh8 * 8;
                int chA = (2 * h + lk) ^ ((rA >> 1) & 3);
                ldsm_x4(af[i][0], af[i][1], af[i][2], af[i][3],
                        asb + (uint32_t)((rA << 4) + (chA << 2)) * 4);
            }
#pragma unroll
            for (int j2 = 0; j2 < 2; j2++) {
                int jsel = lane >> 4;
                int kc   = (lane >> 3) & 1;
                int nB   = wn + j2 * 16 + jsel * 8 + lq;
                int chB  = (2 * h + kc) ^ ((nB >> 1) & 3);
                ldsm_x4(bfr[2 * j2][0], bfr[2 * j2][1],
                        bfr[2 * j2 + 1][0], bfr[2 * j2 + 1][1],
                        wsb + (uint32_t)((nB << 4) + (chB << 2)) * 4);
            }
#pragma unroll
            for (int i = 0; i < ATM; i++)
#pragma unroll
                for (int j = 0; j < 4; j++)
                    mma_bf16(acc[i][j][0], acc[i][j][1], acc[i][j][2], acc[i][j][3],
                             af[i][0], af[i][1], af[i][2], af[i][3],
                             bfr[j][0], bfr[j][1]);
        }
    }

#pragma unroll
    for (int i = 0; i < ATM; i++) {
        int rA = row0 + wm + i * 16 + gid;
#pragma unroll
        for (int j = 0; j < 4; j++) {
            int col = col0 + wn + j * 8 + tig * 2;
            float b0 = 0.f, b1 = 0.f;
            if (HAS_BIAS) { b0 = bias[col]; b1 = bias[col + 1]; }
            float v0 = acc[i][j][0] + b0;
            float v1 = acc[i][j][1] + b1;
            float v2 = acc[i][j][2] + b0;
            float v3 = acc[i][j][3] + b1;
            if (ACT == 1) { v0 = softplus_f(v0); v1 = softplus_f(v1);
                            v2 = softplus_f(v2); v3 = softplus_f(v3); }
            else if (ACT == 2) { v0 = gelu_f(v0); v1 = gelu_f(v1);
                                 v2 = gelu_f(v2); v3 = gelu_f(v3); }
            if (HAS_RES) {
                float2 r0 = *(const float2*)&res[(size_t)rA * N + col];
                float2 r1 = *(const float2*)&res[(size_t)(rA + 8) * N + col];
                v0 += r0.x; v1 += r0.y; v2 += r1.x; v3 += r1.y;
            }
            if (OUT_BF) {
                __nv_bfloat162 p0; p0.x = __float2bfloat16(v0); p0.y = __float2bfloat16(v1);
                __nv_bfloat162 p1; p1.x = __float2bfloat16(v2); p1.y = __float2bfloat16(v3);
                *(__nv_bfloat162*)&CoutBf[(size_t)rA * N + col]       = p0;
                *(__nv_bfloat162*)&CoutBf[(size_t)(rA + 8) * N + col] = p1;
            } else {
                *(float2*)&Cout[(size_t)rA * N + col]       = make_float2(v0, v1);
                *(float2*)&Cout[(size_t)(rA + 8) * N + col] = make_float2(v2, v3);
            }
        }
    }
}

// ------ depthwise 3x3 conv v2: register sliding window along w ----------------
// block = (b, h, w-chunk of 8), 384 threads (one per d). Weights hoisted once
// per 8 outputs; 3 new loads per output (vs 9+9). Zero-taps are exact no-ops.
__global__ __launch_bounds__(DI)
void conv_silu_kernel(const float* __restrict__ xz,
                      const float* __restrict__ cw,
                      const float* __restrict__ cb,
                      const int* __restrict__ perm_rev,
                      float* __restrict__ u,
                      bf16* __restrict__ ubf) {
    int blk = blockIdx.x;            // ((b*32 + h)*4 + q)
    int q   = blk & 3;
    int bh  = blk >> 2;
    int b   = bh >> 5;
    int h   = bh & 31;
    int w0  = q * 8;
    int d   = threadIdx.x;

    float wreg[9];
#pragma unroll
    for (int k = 0; k < 9; k++) wreg[k] = cw[d * 9 + k];
    float bias = cb[d];

    bool ok0 = h > 0, ok2 = h < 31;
    const float* r0 = xz + (size_t)((b << 10) + ((h - 1) << 5)) * (2 * DI) + d;
    const float* r1 = r0 + 32 * (2 * DI);
    const float* r2 = r1 + 32 * (2 * DI);

    // window: a = col w-1, bb = col w, c = col w+1 (rows h-1,h,h+1)
    float a0, a1, a2, bb0, bb1, bb2;
    if (w0 > 0) {
        int off = (w0 - 1) * (2 * DI);
        a0 = ok0 ? r0[off] : 0.f; a1 = r1[off]; a2 = ok2 ? r2[off] : 0.f;
    } else { a0 = a1 = a2 = 0.f; }
    {
        int off = w0 * (2 * DI);
        bb0 = ok0 ? r0[off] : 0.f; bb1 = r1[off]; bb2 = ok2 ? r2[off] : 0.f;
    }

#pragma unroll
    for (int wi = 0; wi < 8; wi++) {
        int w = w0 + wi;
        float c0, c1, c2;
        if (w + 1 < 32) {
            int off = (w + 1) * (2 * DI);
            c0 = ok0 ? r0[off] : 0.f; c1 = r1[off]; c2 = ok2 ? r2[off] : 0.f;
        } else { c0 = c1 = c2 = 0.f; }
        float acc = bias;
        acc = fmaf(wreg[0], a0, acc); acc = fmaf(wreg[1], bb0, acc); acc = fmaf(wreg[2], c0, acc);
        acc = fmaf(wreg[3], a1, acc); acc = fmaf(wreg[4], bb1, acc); acc = fmaf(wreg[5], c1, acc);
        acc = fmaf(wreg[6], a2, acc); acc = fmaf(wreg[7], bb2, acc); acc = fmaf(wreg[8], c2, acc);
        float v = silu_f(acc);
        int o = ((b << 10) + perm_rev[(h << 5) + w]) * DI + d;
        u[o]   = v;
        ubf[o] = __float2bfloat16(v);
        a0 = bb0; a1 = bb1; a2 = bb2;
        bb0 = c0; bb1 = c1; bb2 = c2;
    }
}

// -------- dt_proj + softplus -> packed scan inputs (delta, u) float2 ----------
__global__ __launch_bounds__(256)
void dt_kernel(const float* __restrict__ xdbl64,  // [ROWS,64]
               const float* __restrict__ u,       // [ROWS,DI]
               const float* __restrict__ dtw,     // [384,12]
               const float* __restrict__ dtb,     // [384]
               float2* __restrict__ sc) {         // [ROWS,DI]
    __shared__ float sdt[16][13];
    int t    = threadIdx.x;
    int row0 = blockIdx.x * 16;
    if (t < 192) {
        int r = t / 12, c = t % 12;
        sdt[r][c] = xdbl64[(row0 + r) * 64 + c];
    }
    __syncthreads();
#pragma unroll
    for (int i = 0; i < 24; i++) {
        int idx = t + i * 256;
        int r   = idx / DI;
        int d   = idx % DI;
        float acc = dtb[d];
        const float* dw = &dtw[d * Rr];
#pragma unroll
        for (int j = 0; j < Rr; j++)
            acc = fmaf(sdt[r][j], dw[j], acc);
        float dl = softplus_f(acc);
        size_t o = (size_t)(row0 + r) * DI + d;
        sc[o] = make_float2(dl, u[o]);
    }
}

// ------- selective scan v3: 4 lanes x 4 states, depth-8 prefetch ring ---------
__global__ __launch_bounds__(32)
void scan_kernel(const float* __restrict__ xdbl,   // [ROWS,64]
                 const float2* __restrict__ sc,    // [ROWS,DI]
                 const float* __restrict__ A_log,
                 const float* __restrict__ Dp,
                 const int* __restrict__ perm,
                 float* __restrict__ y) {
    __shared__ int sperm[Ll];
    int t = threadIdx.x;                  // 32
#pragma unroll
    for (int i = 0; i < 32; i++) sperm[t + i * 32] = perm[t + i * 32];
    __syncwarp();

    int g  = blockIdx.x * 8 + (t >> 2);   // group id: 0..3071
    int sl = t & 3;                       // lane-in-group, owns states 4sl..4sl+3
    int b  = g / DI;
    int d  = g % DI;

    float A2[4];
#pragma unroll
    for (int k = 0; k < 4; k++)
        A2[k] = -expf(A_log[d * Ss + sl * 4 + k]) * 1.4426950408889634f; // *log2e
    float Dd = Dp[d];
    float h0 = 0.f, h1 = 0.f, h2 = 0.f, h3 = 0.f;
    int base = b * Ll;

    const float2* scp = sc + (size_t)base * DI + d;
    const float*  xrow = xdbl + (size_t)base * 64;
    float* yp = y + (size_t)base * DI + d;

    // depth-8 prefetch ring
    float2 dd[8]; float4 Bv[8], Cv[8];
#pragma unroll
    for (int j = 0; j < 8; j++) {
        dd[j] = scp[(size_t)j * DI];
        Bv[j] = *(const float4*)(xrow + j * 64 + Rr + sl * 4);
        Cv[j] = *(const float4*)(xrow + j * 64 + Rr + Ss + sl * 4);
    }

    for (int l0 = 0; l0 < Ll; l0 += 8) {
#pragma unroll
        for (int j = 0; j < 8; j++) {
            int l = l0 + j;
            float dl = dd[j].x;
            float du = dl * dd[j].y;
            float uD = dd[j].y * Dd;
            h0 = fmaf(exp2f(dl * A2[0]), h0, du * Bv[j].x);
            h1 = fmaf(exp2f(dl * A2[1]), h1, du * Bv[j].y);
            h2 = fmaf(exp2f(dl * A2[2]), h2, du * Bv[j].z);
            h3 = fmaf(exp2f(dl * A2[3]), h3, du * Bv[j].w);
            float p = h0 * Cv[j].x;
            p = fmaf(h1, Cv[j].y, p);
            p = fmaf(h2, Cv[j].z, p);
            p = fmaf(h3, Cv[j].w, p);
            int ln = l + 8;
            if (ln < Ll) {
                dd[j] = scp[(size_t)ln * DI];
                Bv[j] = *(const float4*)(xrow + ln * 64 + Rr + sl * 4);
                Cv[j] = *(const float4*)(xrow + ln * 64 + Rr + Ss + sl * 4);
            }
            p += __shfl_xor_sync(0xffffffffu, p, 1, 4);
            p += __shfl_xor_sync(0xffffffffu, p, 2, 4);
            if (sl == 0) yp[(size_t)sperm[l] * DI] = p + uD;
        }
    }
}

// ---------------- launcher ----------------
extern "C" void kernel_launch(void* const* d_in, const int* in_sizes, int n_in,
                              void* d_out, int out_size) {
    const float* x          = (const float*)d_in[0];
    const int*   perm       = (const int*)  d_in[1];
    const int*   perm_rev   = (const int*)  d_in[2];
    const float* ln1_g      = (const float*)d_in[3];
    const float* ln1_b      = (const float*)d_in[4];
    const float* in_proj_w  = (const float*)d_in[5];
    const float* conv_w     = (const float*)d_in[6];
    const float* conv_b     = (const float*)d_in[7];
    const float* x_proj_w   = (const float*)d_in[8];
    const float* dt_proj_w  = (const float*)d_in[9];
    const float* dt_proj_b  = (const float*)d_in[10];
    const float* A_log      = (const float*)d_in[11];
    const float* Dp         = (const float*)d_in[12];
    const float* out_norm_g = (const float*)d_in[13];
    const float* out_norm_b = (const float*)d_in[14];
    const float* out_proj_w = (const float*)d_in[15];
    const float* ln2_g      = (const float*)d_in[16];
    const float* ln2_b      = (const float*)d_in[17];
    const float* fc1_w      = (const float*)d_in[18];
    const float* fc1_b      = (const float*)d_in[19];
    const float* fc2_w      = (const float*)d_in[20];
    const float* fc2_b      = (const float*)d_in[21];
    float* out = (float*)d_out;

    bf16 *hx, *ubf, *xw64, *ybf, *h2, *m, *w_in, *w_out, *w_fc1, *w_fc2;
    float *xz, *u, *xdbl, *y, *xmid;
    float2* sc;
    cudaGetSymbolAddress((void**)&hx,    g_hx_bf);
    cudaGetSymbolAddress((void**)&xz,    g_xz);
    cudaGetSymbolAddress((void**)&u,     g_u);
    cudaGetSymbolAddress((void**)&ubf,   g_u_bf);
    cudaGetSymbolAddress((void**)&xw64,  g_xw64);
    cudaGetSymbolAddress((void**)&xdbl,  g_xdbl);
    cudaGetSymbolAddress((void**)&sc,    g_sc);
    cudaGetSymbolAddress((void**)&y,     g_y);
    cudaGetSymbolAddress((void**)&ybf,   g_y_bf);
    cudaGetSymbolAddress((void**)&xmid,  g_xmid);
    cudaGetSymbolAddress((void**)&h2,    g_h2_bf);
    cudaGetSymbolAddress((void**)&m,     g_m_bf);
    cudaGetSymbolAddress((void**)&w_in,  g_w_in);
    cudaGetSymbolAddress((void**)&w_out, g_w_out);
    cudaGetSymbolAddress((void**)&w_fc1, g_w_fc1);
    cudaGetSymbolAddress((void**)&w_fc2, g_w_fc2);

    // 0. weights -> bf16 (incl. padded x_proj weights)
    cvtw_kernel<<<(HID * Cc + 255) / 256, 256>>>(
        in_proj_w, w_in, (2 * DI) * Cc,
        out_proj_w, w_out, Cc * DI,
        fc1_w, w_fc1, HID * Cc,
        fc2_w, w_fc2, Cc * HID,
        x_proj_w, xw64);
    // 1. LN1 -> bf16
    ln_kernel<Cc><<<ROWS, Cc>>>(x, ln1_g, ln1_b, hx);
    // 2. in_proj (TBN=64): [8192,192] x [768,192]^T -> xz fp32
    gemm_bf<64, 0, false, false, false><<<dim3((2 * DI) / 64, ROWS / TBM), 256>>>(
        hx, Cc, w_in, nullptr, nullptr, xz, nullptr, ROWS, 2 * DI, Cc);
    // 3. depthwise conv v2 (sliding window) -> u fp32 + bf16  (PROFILED)
    conv_silu_kernel<<<Bn * Hh * 4, DI>>>(xz, conv_w, conv_b, perm_rev, u, ubf);
    // 4. x_proj: [8192,384] x [64,384]^T -> xdbl fp32
    gemm_bf<32, 0, false, false, false><<<dim3(2, ROWS / TBM), 256>>>(
        ubf, DI, xw64, nullptr, nullptr, xdbl, nullptr, ROWS, 64, DI);
    // 5. dt_proj + softplus -> packed (delta,u) scan inputs
    dt_kernel<<<ROWS / 16, 256>>>(xdbl, u, dt_proj_w, dt_proj_b, sc);
    // 6. selective scan v3 (4x4, depth-8 ring) -> y
    scan_kernel<<<(Bn * DI) / 8, 32>>>(xdbl, sc, A_log, Dp, perm, y);
    // 7. out_norm LN + silu(z) gate -> ybf
    gate_ln_kernel<<<ROWS, DI>>>(y, xz, out_norm_g, out_norm_b, ybf);
    // 8. out_proj + residual x -> xmid fp32 (TBN=32 -> 384 blocks)
    gemm_bf<32, 0, false, true, false><<<dim3(Cc / 32, ROWS / TBM), 256>>>(
        ybf, DI, w_out, nullptr, x, xmid, nullptr, ROWS, Cc, DI);
    // 9. LN2 -> bf16
    ln_kernel<Cc><<<ROWS, Cc>>>(xmid, ln2_g, ln2_b, h2);
    // 10. fc1 (TBN=64) + bias + gelu -> m bf16
    gemm_bf<64, 2, true, false, true><<<dim3(HID / 64, ROWS / TBM), 256>>>(
        h2, Cc, w_fc1, fc1_b, nullptr, nullptr, m, ROWS, HID, Cc);
    // 11. fc2 + bias + residual xmid -> out fp32 (TBN=32 -> 384 blocks)
    gemm_bf<32, 0, true, true, false><<<dim3(Cc / 32, ROWS / TBM), 256>>>(
        m, HID, w_fc2, fc2_b, xmid, out, nullptr, ROWS, Cc, HID);
}